// round 15
// baseline (speedup 1.0000x reference)
#include <cuda_runtime.h>
#include <math.h>

#define BB 8
#define NN 20
#define TT 300
#define NTK 6000
#define UU 64
#define HH 512
#define FEPS 1e-13f

// ---- scratch (static device globals; no allocation) ----
__device__ float g_scores[BB * NTK * UU];
__device__ float g_attn  [BB * NTK * UU];
__device__ float g_wT    [BB * NTK * UU];
__device__ float g_part  [BB * NN * UU * HH];
__device__ float g_aggdoc[BB * UU * HH];

// ---- packed f32x2 FMA helpers (sm_103a) ----
__device__ __forceinline__ unsigned long long pk2(float lo, float hi) {
    unsigned long long r;
    asm("mov.b64 %0, {%1,%2};" : "=l"(r) : "f"(lo), "f"(hi));
    return r;
}
__device__ __forceinline__ void up2(unsigned long long v, float& lo, float& hi) {
    asm("mov.b64 {%0,%1}, %2;" : "=f"(lo), "=f"(hi) : "l"(v));
}
__device__ __forceinline__ unsigned long long fma2(unsigned long long a,
                                                   unsigned long long b,
                                                   unsigned long long c) {
    unsigned long long d;
    asm("fma.rn.f32x2 %0, %1, %2, %3;" : "=l"(d) : "l"(a), "l"(b), "l"(c));
    return d;
}

// =====================================================================
// K1: scores[b,m,u] = sum_h doc[b,m,h]*q[b,u,h]; fused masked softmax
//     over U -> g_attn; raw scores -> g_scores.
// grid (94, 8), 256 threads. 64x64 tile, BK=32, 4x4 per thread (fma2).
// =====================================================================
__global__ __launch_bounds__(256)
void k1_scores(const float* __restrict__ doc, const float* __restrict__ q,
               const int* __restrict__ qmask)
{
    const int b  = blockIdx.y;
    const int m0 = blockIdx.x * 64;
    const int tid = threadIdx.x;
    const int tx = tid & 15, ty = tid >> 4;

    __shared__ float As[64][33];  // [m][k]
    __shared__ float Bs[32][65];  // [k][u]

    const float* db = doc + (size_t)b * NTK * HH;
    const float* qb = q   + (size_t)b * UU  * HH;

    unsigned long long acc[4][2];
#pragma unroll
    for (int i = 0; i < 4; ++i) { acc[i][0] = 0ull; acc[i][1] = 0ull; }

    for (int kc = 0; kc < HH; kc += 32) {
#pragma unroll
        for (int it = 0; it < 2; ++it) {
            int idx = tid + it * 256;            // 0..511
            int r = idx >> 3, c4 = (idx & 7) * 4;
            int m = m0 + r; if (m >= NTK) m = NTK - 1;
            float4 v = *(const float4*)(db + (size_t)m * HH + kc + c4);
            As[r][c4] = v.x; As[r][c4+1] = v.y; As[r][c4+2] = v.z; As[r][c4+3] = v.w;
        }
#pragma unroll
        for (int it = 0; it < 2; ++it) {
            int idx = tid + it * 256;
            int u = idx >> 3, c4 = (idx & 7) * 4;
            float4 v = *(const float4*)(qb + (size_t)u * HH + kc + c4);
            Bs[c4][u] = v.x; Bs[c4+1][u] = v.y; Bs[c4+2][u] = v.z; Bs[c4+3][u] = v.w;
        }
        __syncthreads();
#pragma unroll
        for (int k = 0; k < 32; ++k) {
            float b0 = Bs[k][tx*4+0], b1 = Bs[k][tx*4+1];
            float b2 = Bs[k][tx*4+2], b3 = Bs[k][tx*4+3];
            unsigned long long bp0 = pk2(b0, b1), bp1 = pk2(b2, b3);
            float a0 = As[ty*4+0][k], a1 = As[ty*4+1][k];
            float a2 = As[ty*4+2][k], a3 = As[ty*4+3][k];
            unsigned long long p;
            p = pk2(a0, a0); acc[0][0]=fma2(p,bp0,acc[0][0]); acc[0][1]=fma2(p,bp1,acc[0][1]);
            p = pk2(a1, a1); acc[1][0]=fma2(p,bp0,acc[1][0]); acc[1][1]=fma2(p,bp1,acc[1][1]);
            p = pk2(a2, a2); acc[2][0]=fma2(p,bp0,acc[2][0]); acc[2][1]=fma2(p,bp1,acc[2][1]);
            p = pk2(a3, a3); acc[3][0]=fma2(p,bp0,acc[3][0]); acc[3][1]=fma2(p,bp1,acc[3][1]);
        }
        __syncthreads();
    }

    float qmf[4];
#pragma unroll
    for (int j = 0; j < 4; ++j) qmf[j] = (float)qmask[b * UU + tx * 4 + j];

#pragma unroll
    for (int i = 0; i < 4; ++i) {
        float s[4];
        up2(acc[i][0], s[0], s[1]);
        up2(acc[i][1], s[2], s[3]);
        float x[4], mx = -3.4e38f;
#pragma unroll
        for (int j = 0; j < 4; ++j) { x[j] = s[j] * qmf[j]; mx = fmaxf(mx, x[j]); }
#pragma unroll
        for (int o = 1; o < 16; o <<= 1)
            mx = fmaxf(mx, __shfl_xor_sync(0xffffffffu, mx, o));
        float e[4], z = 0.f, zm = 0.f;
#pragma unroll
        for (int j = 0; j < 4; ++j) {
            e[j] = expf(x[j] - mx);
            z += e[j]; zm += qmf[j] * e[j];
        }
#pragma unroll
        for (int o = 1; o < 16; o <<= 1) {
            z  += __shfl_xor_sync(0xffffffffu, z,  o);
            zm += __shfl_xor_sync(0xffffffffu, zm, o);
        }
        float inv = 1.0f / (zm + FEPS * z);
        int m = m0 + ty * 4 + i;
        if (m < NTK) {
            size_t off = ((size_t)b * NTK + m) * UU + tx * 4;
            *(float4*)(g_scores + off) = make_float4(s[0], s[1], s[2], s[3]);
            *(float4*)(g_attn + off) = make_float4(qmf[0]*e[0]*inv, qmf[1]*e[1]*inv,
                                                   qmf[2]*e[2]*inv, qmf[3]*e[3]*inv);
        }
    }
}

// =====================================================================
// K2: softmax over T per (b,n,u), masked by doc_mask -> g_wT
// grid (20, 8), 256 threads
// =====================================================================
__global__ __launch_bounds__(256)
void k2_softT(const int* __restrict__ dmask)
{
    const int n = blockIdx.x, b = blockIdx.y;
    __shared__ float sdm[TT];
    __shared__ float red [4][64];
    __shared__ float red2[4][64];
    __shared__ float fmx[64], finv[64];

    const int tid = threadIdx.x;
    for (int t = tid; t < TT; t += 256)
        sdm[t] = (float)dmask[(b * NN + n) * TT + t];
    __syncthreads();

    const int u = tid & 63, sl = tid >> 6;
    const float* S = g_scores + ((size_t)b * NTK + n * TT) * UU;

    float mx = -3.4e38f;
    for (int t = sl; t < TT; t += 4)
        mx = fmaxf(mx, S[t * UU + u] * sdm[t]);
    red[sl][u] = mx;
    __syncthreads();
    if (tid < 64)
        fmx[u] = fmaxf(fmaxf(red[0][u], red[1][u]), fmaxf(red[2][u], red[3][u]));
    __syncthreads();

    float m = fmx[u];
    float z = 0.f, zm = 0.f;
    for (int t = sl; t < TT; t += 4) {
        float dm = sdm[t];
        float e = expf(S[t * UU + u] * dm - m);
        z += e; zm += dm * e;
    }
    red[sl][u] = z; red2[sl][u] = zm;
    __syncthreads();
    if (tid < 64) {
        float Z  = red [0][u] + red [1][u] + red [2][u] + red [3][u];
        float Zm = red2[0][u] + red2[1][u] + red2[2][u] + red2[3][u];
        finv[u] = 1.0f / (Zm + FEPS * Z);
    }
    __syncthreads();

    float inv = finv[u];
    float* W = g_wT + ((size_t)b * NTK + n * TT) * UU;
    for (int t = sl; t < TT; t += 4) {
        float dm = sdm[t];
        float e = expf(S[t * UU + u] * dm - m);
        W[t * UU + u] = dm * e * inv;
    }
}

// =====================================================================
// K3: partial aggdoc per (b, n, hblock): part[b,n,u,h] = sum_t wT*doc
// grid (8, 20, 8), 256 threads. 64(u)x64(h), BK=20.
// =====================================================================
__global__ __launch_bounds__(256)
void k3_part(const float* __restrict__ doc)
{
    const int hb = blockIdx.x, n = blockIdx.y, b = blockIdx.z;
    const int tid = threadIdx.x;
    const int tx = tid & 15, ty = tid >> 4;
    const int h0 = hb * 64;

    __shared__ float Aw[20][65];  // [k][u]
    __shared__ float Bd[20][68];  // [k][h]

    const float* W = g_wT + ((size_t)b * NTK + n * TT) * UU;
    const float* D = doc + ((size_t)b * NTK + n * TT) * HH + h0;

    unsigned long long acc[4][2];
#pragma unroll
    for (int i = 0; i < 4; ++i) { acc[i][0] = 0ull; acc[i][1] = 0ull; }

    for (int kk = 0; kk < TT; kk += 20) {
#pragma unroll
        for (int it = 0; it < 2; ++it) {
            int idx = tid + it * 256;
            if (idx < 320) {
                int r = idx >> 4, c4 = (idx & 15) * 4;
                float4 v = *(const float4*)(W + (size_t)(kk + r) * UU + c4);
                Aw[r][c4] = v.x; Aw[r][c4+1] = v.y; Aw[r][c4+2] = v.z; Aw[r][c4+3] = v.w;
            }
        }
#pragma unroll
        for (int it = 0; it < 2; ++it) {
            int idx = tid + it * 256;
            if (idx < 320) {
                int r = idx >> 4, c4 = (idx & 15) * 4;
                float4 v = *(const float4*)(D + (size_t)(kk + r) * HH + c4);
                Bd[r][c4] = v.x; Bd[r][c4+1] = v.y; Bd[r][c4+2] = v.z; Bd[r][c4+3] = v.w;
            }
        }
        __syncthreads();
#pragma unroll
        for (int k = 0; k < 20; ++k) {
            float b0 = Bd[k][tx*4+0], b1 = Bd[k][tx*4+1];
            float b2 = Bd[k][tx*4+2], b3 = Bd[k][tx*4+3];
            unsigned long long bp0 = pk2(b0, b1), bp1 = pk2(b2, b3);
            float a0 = Aw[k][ty*4+0], a1 = Aw[k][ty*4+1];
            float a2 = Aw[k][ty*4+2], a3 = Aw[k][ty*4+3];
            unsigned long long p;
            p = pk2(a0, a0); acc[0][0]=fma2(p,bp0,acc[0][0]); acc[0][1]=fma2(p,bp1,acc[0][1]);
            p = pk2(a1, a1); acc[1][0]=fma2(p,bp0,acc[1][0]); acc[1][1]=fma2(p,bp1,acc[1][1]);
            p = pk2(a2, a2); acc[2][0]=fma2(p,bp0,acc[2][0]); acc[2][1]=fma2(p,bp1,acc[2][1]);
            p = pk2(a3, a3); acc[3][0]=fma2(p,bp0,acc[3][0]); acc[3][1]=fma2(p,bp1,acc[3][1]);
        }
        __syncthreads();
    }

#pragma unroll
    for (int i = 0; i < 4; ++i) {
        float v0, v1, v2, v3;
        up2(acc[i][0], v0, v1);
        up2(acc[i][1], v2, v3);
        size_t off = (((size_t)(b * NN + n) * UU) + ty * 4 + i) * HH + h0 + tx * 4;
        *(float4*)(g_part + off) = make_float4(v0, v1, v2, v3);
    }
}

// =====================================================================
// K3b: aggdoc[b,u,h] = sum_n part[b,n,u,h].  grid 1024 x 256
// =====================================================================
__global__ __launch_bounds__(256)
void k3b_reduce()
{
    int idx = blockIdx.x * 256 + threadIdx.x;   // < 8*64*512
    int b = idx >> 15;
    int r = idx & 32767;
    const float* P = g_part + (size_t)b * NN * UU * HH + r;
    float s = 0.f;
#pragma unroll
    for (int n = 0; n < NN; ++n) s += P[(size_t)n * UU * HH];
    g_aggdoc[(size_t)b * UU * HH + r] = s;
}

// =====================================================================
// K4: out[b,m, 0:512] = attn @ q ; out[b,m, 512:1024] = attn @ aggdoc
// grid (8, 94, 8), 256 threads. 64x64 tiles, K=64 resident.
// =====================================================================
__global__ __launch_bounds__(256)
void k4_out(const float* __restrict__ q, float* __restrict__ out)
{
    const int hb = blockIdx.x;
    const int m0 = blockIdx.y * 64;
    const int b  = blockIdx.z;
    const int tid = threadIdx.x;
    const int tx = tid & 15, ty = tid >> 4;
    const int h0 = hb * 64;

    __shared__ float Aa[64][65];  // [m][u]
    __shared__ float Bt[64][68];  // [u][h]

    const float* At = g_attn + (size_t)b * NTK * UU;
#pragma unroll
    for (int it = 0; it < 4; ++it) {
        int idx = tid + it * 256;            // 0..1023
        int r = idx >> 4, c4 = (idx & 15) * 4;
        int m = m0 + r; if (m >= NTK) m = NTK - 1;
        float4 v = *(const float4*)(At + (size_t)m * UU + c4);
        Aa[r][c4] = v.x; Aa[r][c4+1] = v.y; Aa[r][c4+2] = v.z; Aa[r][c4+3] = v.w;
    }

    const float* src0 = q        + (size_t)b * UU * HH + h0;
    const float* src1 = g_aggdoc + (size_t)b * UU * HH + h0;

#pragma unroll
    for (int half = 0; half < 2; ++half) {
        const float* Bsrc = (half == 0) ? src0 : src1;
        __syncthreads();
#pragma unroll
        for (int it = 0; it < 4; ++it) {
            int idx = tid + it * 256;
            int r = idx >> 4, c4 = (idx & 15) * 4;
            float4 v = *(const float4*)(Bsrc + (size_t)r * HH + c4);
            Bt[r][c4] = v.x; Bt[r][c4+1] = v.y; Bt[r][c4+2] = v.z; Bt[r][c4+3] = v.w;
        }
        __syncthreads();

        unsigned long long acc[4][2];
#pragma unroll
        for (int i = 0; i < 4; ++i) { acc[i][0] = 0ull; acc[i][1] = 0ull; }

#pragma unroll 8
        for (int k = 0; k < 64; ++k) {
            float b0 = Bt[k][tx*4+0], b1 = Bt[k][tx*4+1];
            float b2 = Bt[k][tx*4+2], b3 = Bt[k][tx*4+3];
            unsigned long long bp0 = pk2(b0, b1), bp1 = pk2(b2, b3);
            float a0 = Aa[ty*4+0][k], a1 = Aa[ty*4+1][k];
            float a2 = Aa[ty*4+2][k], a3 = Aa[ty*4+3][k];
            unsigned long long p;
            p = pk2(a0, a0); acc[0][0]=fma2(p,bp0,acc[0][0]); acc[0][1]=fma2(p,bp1,acc[0][1]);
            p = pk2(a1, a1); acc[1][0]=fma2(p,bp0,acc[1][0]); acc[1][1]=fma2(p,bp1,acc[1][1]);
            p = pk2(a2, a2); acc[2][0]=fma2(p,bp0,acc[2][0]); acc[2][1]=fma2(p,bp1,acc[2][1]);
            p = pk2(a3, a3); acc[3][0]=fma2(p,bp0,acc[3][0]); acc[3][1]=fma2(p,bp1,acc[3][1]);
        }

        int hout = half * 512 + h0 + tx * 4;
#pragma unroll
        for (int i = 0; i < 4; ++i) {
            int m = m0 + ty * 4 + i;
            if (m < NTK) {
                float v0, v1, v2, v3;
                up2(acc[i][0], v0, v1);
                up2(acc[i][1], v2, v3);
                *(float4*)(out + ((size_t)b * NTK + m) * 1024 + hout) =
                    make_float4(v0, v1, v2, v3);
            }
        }
    }
}

// =====================================================================
extern "C" void kernel_launch(void* const* d_in, const int* in_sizes, int n_in,
                              void* d_out, int out_size)
{
    const float* doc   = (const float*)d_in[0];   // B,N,T,H
    const float* q     = (const float*)d_in[1];   // B,U,H
    const int*   dmask = (const int*)  d_in[2];   // B,N,T
    const int*   qmask = (const int*)  d_in[3];   // B,U
    float* out = (float*)d_out;                   // B,N,T,2H

    k1_scores<<<dim3(94, BB), 256>>>(doc, q, qmask);
    k2_softT <<<dim3(NN, BB), 256>>>(dmask);
    k3_part  <<<dim3(8, NN, BB), 256>>>(doc);
    k3b_reduce<<<1024, 256>>>();
    k4_out   <<<dim3(8, 94, BB), 256>>>(q, out);
}

// round 16
// speedup vs baseline: 1.5353x; 1.5353x over previous
#include <cuda_runtime.h>
#include <math.h>

#define BB 8
#define NN 20
#define TT 300
#define NTK 6000
#define UU 64
#define HH 512
#define FEPS 1e-13f

// ---- scratch (static device globals; no allocation) ----
__device__ float g_scores[BB * NTK * UU];
__device__ float g_attn  [BB * NTK * UU];
__device__ float g_wT    [BB * NTK * UU];
__device__ float g_part  [BB * NN * UU * HH];
__device__ float g_aggdoc[BB * UU * HH];

// ---- packed f32x2 FMA helpers (sm_103a) ----
__device__ __forceinline__ unsigned long long pk2(float lo, float hi) {
    unsigned long long r;
    asm("mov.b64 %0, {%1,%2};" : "=l"(r) : "f"(lo), "f"(hi));
    return r;
}
__device__ __forceinline__ void up2(unsigned long long v, float& lo, float& hi) {
    asm("mov.b64 {%0,%1}, %2;" : "=f"(lo), "=f"(hi) : "l"(v));
}
__device__ __forceinline__ unsigned long long fma2(unsigned long long a,
                                                   unsigned long long b,
                                                   unsigned long long c) {
    unsigned long long d;
    asm("fma.rn.f32x2 %0, %1, %2, %3;" : "=l"(d) : "l"(a), "l"(b), "l"(c));
    return d;
}

// =====================================================================
// K1: scores[b,m,u] = sum_h doc[b,m,h]*q[b,u,h]; fused masked softmax
//     over U -> g_attn; raw scores -> g_scores.
// grid (94, 8), 256 threads. 64x64 tile, BK=32, 4x4 per thread (fma2).
// =====================================================================
__global__ __launch_bounds__(256)
void k1_scores(const float* __restrict__ doc, const float* __restrict__ q,
               const int* __restrict__ qmask)
{
    const int b  = blockIdx.y;
    const int m0 = blockIdx.x * 64;
    const int tid = threadIdx.x;
    const int tx = tid & 15, ty = tid >> 4;

    __shared__ float As[64][33];  // [m][k]
    __shared__ float Bs[32][65];  // [k][u]

    const float* db = doc + (size_t)b * NTK * HH;
    const float* qb = q   + (size_t)b * UU  * HH;

    unsigned long long acc[4][2];
#pragma unroll
    for (int i = 0; i < 4; ++i) { acc[i][0] = 0ull; acc[i][1] = 0ull; }

    for (int kc = 0; kc < HH; kc += 32) {
#pragma unroll
        for (int it = 0; it < 2; ++it) {
            int idx = tid + it * 256;            // 0..511
            int r = idx >> 3, c4 = (idx & 7) * 4;
            int m = m0 + r; if (m >= NTK) m = NTK - 1;
            float4 v = *(const float4*)(db + (size_t)m * HH + kc + c4);
            As[r][c4] = v.x; As[r][c4+1] = v.y; As[r][c4+2] = v.z; As[r][c4+3] = v.w;
        }
#pragma unroll
        for (int it = 0; it < 2; ++it) {
            int idx = tid + it * 256;
            int u = idx >> 3, c4 = (idx & 7) * 4;
            float4 v = *(const float4*)(qb + (size_t)u * HH + kc + c4);
            Bs[c4][u] = v.x; Bs[c4+1][u] = v.y; Bs[c4+2][u] = v.z; Bs[c4+3][u] = v.w;
        }
        __syncthreads();
#pragma unroll
        for (int k = 0; k < 32; ++k) {
            float b0 = Bs[k][tx*4+0], b1 = Bs[k][tx*4+1];
            float b2 = Bs[k][tx*4+2], b3 = Bs[k][tx*4+3];
            unsigned long long bp0 = pk2(b0, b1), bp1 = pk2(b2, b3);
            float a0 = As[ty*4+0][k], a1 = As[ty*4+1][k];
            float a2 = As[ty*4+2][k], a3 = As[ty*4+3][k];
            unsigned long long p;
            p = pk2(a0, a0); acc[0][0]=fma2(p,bp0,acc[0][0]); acc[0][1]=fma2(p,bp1,acc[0][1]);
            p = pk2(a1, a1); acc[1][0]=fma2(p,bp0,acc[1][0]); acc[1][1]=fma2(p,bp1,acc[1][1]);
            p = pk2(a2, a2); acc[2][0]=fma2(p,bp0,acc[2][0]); acc[2][1]=fma2(p,bp1,acc[2][1]);
            p = pk2(a3, a3); acc[3][0]=fma2(p,bp0,acc[3][0]); acc[3][1]=fma2(p,bp1,acc[3][1]);
        }
        __syncthreads();
    }

    float qmf[4];
#pragma unroll
    for (int j = 0; j < 4; ++j) qmf[j] = (float)qmask[b * UU + tx * 4 + j];

#pragma unroll
    for (int i = 0; i < 4; ++i) {
        float s[4];
        up2(acc[i][0], s[0], s[1]);
        up2(acc[i][1], s[2], s[3]);
        float x[4], mx = -3.4e38f;
#pragma unroll
        for (int j = 0; j < 4; ++j) { x[j] = s[j] * qmf[j]; mx = fmaxf(mx, x[j]); }
#pragma unroll
        for (int o = 1; o < 16; o <<= 1)
            mx = fmaxf(mx, __shfl_xor_sync(0xffffffffu, mx, o));
        float e[4], z = 0.f, zm = 0.f;
#pragma unroll
        for (int j = 0; j < 4; ++j) {
            e[j] = expf(x[j] - mx);
            z += e[j]; zm += qmf[j] * e[j];
        }
#pragma unroll
        for (int o = 1; o < 16; o <<= 1) {
            z  += __shfl_xor_sync(0xffffffffu, z,  o);
            zm += __shfl_xor_sync(0xffffffffu, zm, o);
        }
        float inv = 1.0f / (zm + FEPS * z);
        int m = m0 + ty * 4 + i;
        if (m < NTK) {
            size_t off = ((size_t)b * NTK + m) * UU + tx * 4;
            *(float4*)(g_scores + off) = make_float4(s[0], s[1], s[2], s[3]);
            *(float4*)(g_attn + off) = make_float4(qmf[0]*e[0]*inv, qmf[1]*e[1]*inv,
                                                   qmf[2]*e[2]*inv, qmf[3]*e[3]*inv);
        }
    }
}

// =====================================================================
// K2: softmax over T per (b,n,u), masked by doc_mask -> g_wT
// grid (20, 8), 256 threads
// =====================================================================
__global__ __launch_bounds__(256)
void k2_softT(const int* __restrict__ dmask)
{
    const int n = blockIdx.x, b = blockIdx.y;
    __shared__ float sdm[TT];
    __shared__ float red [4][64];
    __shared__ float red2[4][64];
    __shared__ float fmx[64], finv[64];

    const int tid = threadIdx.x;
    for (int t = tid; t < TT; t += 256)
        sdm[t] = (float)dmask[(b * NN + n) * TT + t];
    __syncthreads();

    const int u = tid & 63, sl = tid >> 6;
    const float* S = g_scores + ((size_t)b * NTK + n * TT) * UU;

    float mx = -3.4e38f;
    for (int t = sl; t < TT; t += 4)
        mx = fmaxf(mx, S[t * UU + u] * sdm[t]);
    red[sl][u] = mx;
    __syncthreads();
    if (tid < 64)
        fmx[u] = fmaxf(fmaxf(red[0][u], red[1][u]), fmaxf(red[2][u], red[3][u]));
    __syncthreads();

    float m = fmx[u];
    float z = 0.f, zm = 0.f;
    for (int t = sl; t < TT; t += 4) {
        float dm = sdm[t];
        float e = expf(S[t * UU + u] * dm - m);
        z += e; zm += dm * e;
    }
    red[sl][u] = z; red2[sl][u] = zm;
    __syncthreads();
    if (tid < 64) {
        float Z  = red [0][u] + red [1][u] + red [2][u] + red [3][u];
        float Zm = red2[0][u] + red2[1][u] + red2[2][u] + red2[3][u];
        finv[u] = 1.0f / (Zm + FEPS * Z);
    }
    __syncthreads();

    float inv = finv[u];
    float* W = g_wT + ((size_t)b * NTK + n * TT) * UU;
    for (int t = sl; t < TT; t += 4) {
        float dm = sdm[t];
        float e = expf(S[t * UU + u] * dm - m);
        W[t * UU + u] = dm * e * inv;
    }
}

// =====================================================================
// K3: partial aggdoc per (b, n, hblock): part[b,n,u,h] = sum_t wT*doc
// grid (8, 20, 8), 256 threads. 64(u)x64(h), BK=20.
// =====================================================================
__global__ __launch_bounds__(256)
void k3_part(const float* __restrict__ doc)
{
    const int hb = blockIdx.x, n = blockIdx.y, b = blockIdx.z;
    const int tid = threadIdx.x;
    const int tx = tid & 15, ty = tid >> 4;
    const int h0 = hb * 64;

    __shared__ float Aw[20][65];  // [k][u]
    __shared__ float Bd[20][68];  // [k][h]

    const float* W = g_wT + ((size_t)b * NTK + n * TT) * UU;
    const float* D = doc + ((size_t)b * NTK + n * TT) * HH + h0;

    unsigned long long acc[4][2];
#pragma unroll
    for (int i = 0; i < 4; ++i) { acc[i][0] = 0ull; acc[i][1] = 0ull; }

    for (int kk = 0; kk < TT; kk += 20) {
#pragma unroll
        for (int it = 0; it < 2; ++it) {
            int idx = tid + it * 256;
            if (idx < 320) {
                int r = idx >> 4, c4 = (idx & 15) * 4;
                float4 v = *(const float4*)(W + (size_t)(kk + r) * UU + c4);
                Aw[r][c4] = v.x; Aw[r][c4+1] = v.y; Aw[r][c4+2] = v.z; Aw[r][c4+3] = v.w;
            }
        }
#pragma unroll
        for (int it = 0; it < 2; ++it) {
            int idx = tid + it * 256;
            if (idx < 320) {
                int r = idx >> 4, c4 = (idx & 15) * 4;
                float4 v = *(const float4*)(D + (size_t)(kk + r) * HH + c4);
                Bd[r][c4] = v.x; Bd[r][c4+1] = v.y; Bd[r][c4+2] = v.z; Bd[r][c4+3] = v.w;
            }
        }
        __syncthreads();
#pragma unroll
        for (int k = 0; k < 20; ++k) {
            float b0 = Bd[k][tx*4+0], b1 = Bd[k][tx*4+1];
            float b2 = Bd[k][tx*4+2], b3 = Bd[k][tx*4+3];
            unsigned long long bp0 = pk2(b0, b1), bp1 = pk2(b2, b3);
            float a0 = Aw[k][ty*4+0], a1 = Aw[k][ty*4+1];
            float a2 = Aw[k][ty*4+2], a3 = Aw[k][ty*4+3];
            unsigned long long p;
            p = pk2(a0, a0); acc[0][0]=fma2(p,bp0,acc[0][0]); acc[0][1]=fma2(p,bp1,acc[0][1]);
            p = pk2(a1, a1); acc[1][0]=fma2(p,bp0,acc[1][0]); acc[1][1]=fma2(p,bp1,acc[1][1]);
            p = pk2(a2, a2); acc[2][0]=fma2(p,bp0,acc[2][0]); acc[2][1]=fma2(p,bp1,acc[2][1]);
            p = pk2(a3, a3); acc[3][0]=fma2(p,bp0,acc[3][0]); acc[3][1]=fma2(p,bp1,acc[3][1]);
        }
        __syncthreads();
    }

#pragma unroll
    for (int i = 0; i < 4; ++i) {
        float v0, v1, v2, v3;
        up2(acc[i][0], v0, v1);
        up2(acc[i][1], v2, v3);
        size_t off = (((size_t)(b * NN + n) * UU) + ty * 4 + i) * HH + h0 + tx * 4;
        *(float4*)(g_part + off) = make_float4(v0, v1, v2, v3);
    }
}

// =====================================================================
// K3b: aggdoc[b,u,h] = sum_n part[b,n,u,h].  grid 1024 x 256
// =====================================================================
__global__ __launch_bounds__(256)
void k3b_reduce()
{
    int idx = blockIdx.x * 256 + threadIdx.x;   // < 8*64*512
    int b = idx >> 15;
    int r = idx & 32767;
    const float* P = g_part + (size_t)b * NN * UU * HH + r;
    float s = 0.f;
#pragma unroll
    for (int n = 0; n < NN; ++n) s += P[(size_t)n * UU * HH];
    g_aggdoc[(size_t)b * UU * HH + r] = s;
}

// =====================================================================
// K4: out[b,m, 0:512] = attn @ q ; out[b,m, 512:1024] = attn @ aggdoc
// grid (8, 94, 8), 256 threads. 64x64 tiles, K=64 resident.
// =====================================================================
__global__ __launch_bounds__(256)
void k4_out(const float* __restrict__ q, float* __restrict__ out)
{
    const int hb = blockIdx.x;
    const int m0 = blockIdx.y * 64;
    const int b  = blockIdx.z;
    const int tid = threadIdx.x;
    const int tx = tid & 15, ty = tid >> 4;
    const int h0 = hb * 64;

    __shared__ float Aa[64][65];  // [m][u]
    __shared__ float Bt[64][68];  // [u][h]

    const float* At = g_attn + (size_t)b * NTK * UU;
#pragma unroll
    for (int it = 0; it < 4; ++it) {
        int idx = tid + it * 256;            // 0..1023
        int r = idx >> 4, c4 = (idx & 15) * 4;
        int m = m0 + r; if (m >= NTK) m = NTK - 1;
        float4 v = *(const float4*)(At + (size_t)m * UU + c4);
        Aa[r][c4] = v.x; Aa[r][c4+1] = v.y; Aa[r][c4+2] = v.z; Aa[r][c4+3] = v.w;
    }

    const float* src0 = q        + (size_t)b * UU * HH + h0;
    const float* src1 = g_aggdoc + (size_t)b * UU * HH + h0;

#pragma unroll
    for (int half = 0; half < 2; ++half) {
        const float* Bsrc = (half == 0) ? src0 : src1;
        __syncthreads();
#pragma unroll
        for (int it = 0; it < 4; ++it) {
            int idx = tid + it * 256;
            int r = idx >> 4, c4 = (idx & 15) * 4;
            float4 v = *(const float4*)(Bsrc + (size_t)r * HH + c4);
            Bt[r][c4] = v.x; Bt[r][c4+1] = v.y; Bt[r][c4+2] = v.z; Bt[r][c4+3] = v.w;
        }
        __syncthreads();

        unsigned long long acc[4][2];
#pragma unroll
        for (int i = 0; i < 4; ++i) { acc[i][0] = 0ull; acc[i][1] = 0ull; }

#pragma unroll 8
        for (int k = 0; k < 64; ++k) {
            float b0 = Bt[k][tx*4+0], b1 = Bt[k][tx*4+1];
            float b2 = Bt[k][tx*4+2], b3 = Bt[k][tx*4+3];
            unsigned long long bp0 = pk2(b0, b1), bp1 = pk2(b2, b3);
            float a0 = Aa[ty*4+0][k], a1 = Aa[ty*4+1][k];
            float a2 = Aa[ty*4+2][k], a3 = Aa[ty*4+3][k];
            unsigned long long p;
            p = pk2(a0, a0); acc[0][0]=fma2(p,bp0,acc[0][0]); acc[0][1]=fma2(p,bp1,acc[0][1]);
            p = pk2(a1, a1); acc[1][0]=fma2(p,bp0,acc[1][0]); acc[1][1]=fma2(p,bp1,acc[1][1]);
            p = pk2(a2, a2); acc[2][0]=fma2(p,bp0,acc[2][0]); acc[2][1]=fma2(p,bp1,acc[2][1]);
            p = pk2(a3, a3); acc[3][0]=fma2(p,bp0,acc[3][0]); acc[3][1]=fma2(p,bp1,acc[3][1]);
        }

        int hout = half * 512 + h0 + tx * 4;
#pragma unroll
        for (int i = 0; i < 4; ++i) {
            int m = m0 + ty * 4 + i;
            if (m < NTK) {
                float v0, v1, v2, v3;
                up2(acc[i][0], v0, v1);
                up2(acc[i][1], v2, v3);
                *(float4*)(out + ((size_t)b * NTK + m) * 1024 + hout) =
                    make_float4(v0, v1, v2, v3);
            }
        }
    }
}

// =====================================================================
extern "C" void kernel_launch(void* const* d_in, const int* in_sizes, int n_in,
                              void* d_out, int out_size)
{
    const float* doc   = (const float*)d_in[0];   // B,N,T,H
    const float* q     = (const float*)d_in[1];   // B,U,H
    const int*   dmask = (const int*)  d_in[2];   // B,N,T
    const int*   qmask = (const int*)  d_in[3];   // B,U
    float* out = (float*)d_out;                   // B,N,T,2H

    k1_scores<<<dim3(94, BB), 256>>>(doc, q, qmask);
    k2_softT <<<dim3(NN, BB), 256>>>(dmask);
    k3_part  <<<dim3(8, NN, BB), 256>>>(doc);
    k3b_reduce<<<1024, 256>>>();
    k4_out   <<<dim3(8, 94, BB), 256>>>(q, out);
}

// round 17
// speedup vs baseline: 1.6196x; 1.0549x over previous
#include <cuda_runtime.h>
#include <math.h>

#define BB 8
#define NN 20
#define TT 300
#define NTK 6000
#define UU 64
#define HH 512
#define FEPS 1e-13f

typedef unsigned long long ull;

// ---- scratch (static device globals; no allocation) ----
__device__ float g_scores[BB * NTK * UU];   // [b][m][u]
__device__ float g_attnT [BB * UU * NTK];   // [b][u][m]  (transposed!)
__device__ float g_wT    [BB * NTK * UU];   // [b][t-major][u]
__device__ float g_part  [BB * NN * UU * HH];
__device__ float g_aggdoc[BB * UU * HH];

// ---- packed f32x2 helpers ----
__device__ __forceinline__ ull pk2(float lo, float hi) {
    ull r; asm("mov.b64 %0,{%1,%2};" : "=l"(r) : "f"(lo), "f"(hi)); return r;
}
__device__ __forceinline__ void up2(ull v, float& lo, float& hi) {
    asm("mov.b64 {%0,%1},%2;" : "=f"(lo), "=f"(hi) : "l"(v));
}
__device__ __forceinline__ ull fma2(ull a, ull b, ull c) {
    ull d; asm("fma.rn.f32x2 %0,%1,%2,%3;" : "=l"(d) : "l"(a), "l"(b), "l"(c));
    return d;
}

// =====================================================================
// K1: scores = doc @ q^T, fused masked softmax over U.
// Writes g_scores [m][u] and g_attnT [u][m] (smem transpose).
// grid (47, 8), 128 threads. Tile M=128 x U=64, BK=16, 8x8/thread.
// acc[i][j]: i = m-pair (2i,2i+1), j -> u = (j<4 ? tx*4+j : 32+tx*4+j-4)
// =====================================================================
__global__ __launch_bounds__(128)
void k1_scores(const float* __restrict__ doc, const float* __restrict__ q,
               const int* __restrict__ qmask)
{
    const int b = blockIdx.y, m0 = blockIdx.x * 128, tid = threadIdx.x;
    const int tx = tid & 7, tm = tid >> 3;   // tx: u-group, tm: m-group (8 rows)

    __shared__ __align__(16) union SU {
        struct { float As[16][136]; float Bs[16][68]; } s;  // 13056 B
        float sw[128][68];                                  // 34816 B
    } smu;

    const float* db = doc + (size_t)b * NTK * HH;
    const float* qb = q   + (size_t)b * UU  * HH;

    int mld = m0 + tid; if (mld > NTK - 1) mld = NTK - 1;
    const float* drow = db + (size_t)mld * HH;
    const int ustg = tid & 63, khalf = (tid >> 6) * 8;
    const float* qrow = qb + (size_t)ustg * HH;

    ull acc[4][8];
#pragma unroll
    for (int i = 0; i < 4; ++i)
#pragma unroll
        for (int j = 0; j < 8; ++j) acc[i][j] = 0ull;

    for (int kc = 0; kc < HH; kc += 16) {
        // As[k][m]: thread loads its doc row's 16 k-values, scatter-transpose
        float4 v0 = *(const float4*)(drow + kc + 0);
        float4 v1 = *(const float4*)(drow + kc + 4);
        float4 v2 = *(const float4*)(drow + kc + 8);
        float4 v3 = *(const float4*)(drow + kc + 12);
        smu.s.As[ 0][tid]=v0.x; smu.s.As[ 1][tid]=v0.y; smu.s.As[ 2][tid]=v0.z; smu.s.As[ 3][tid]=v0.w;
        smu.s.As[ 4][tid]=v1.x; smu.s.As[ 5][tid]=v1.y; smu.s.As[ 6][tid]=v1.z; smu.s.As[ 7][tid]=v1.w;
        smu.s.As[ 8][tid]=v2.x; smu.s.As[ 9][tid]=v2.y; smu.s.As[10][tid]=v2.z; smu.s.As[11][tid]=v2.w;
        smu.s.As[12][tid]=v3.x; smu.s.As[13][tid]=v3.y; smu.s.As[14][tid]=v3.z; smu.s.As[15][tid]=v3.w;
        // Bs[k][u]: thread u = tid&63, k-half = (tid>>6)*8
        float4 w0 = *(const float4*)(qrow + kc + khalf + 0);
        float4 w1 = *(const float4*)(qrow + kc + khalf + 4);
        smu.s.Bs[khalf+0][ustg]=w0.x; smu.s.Bs[khalf+1][ustg]=w0.y;
        smu.s.Bs[khalf+2][ustg]=w0.z; smu.s.Bs[khalf+3][ustg]=w0.w;
        smu.s.Bs[khalf+4][ustg]=w1.x; smu.s.Bs[khalf+5][ustg]=w1.y;
        smu.s.Bs[khalf+6][ustg]=w1.z; smu.s.Bs[khalf+7][ustg]=w1.w;
        __syncthreads();
#pragma unroll
        for (int k = 0; k < 16; ++k) {
            ulonglong2 A0 = *(const ulonglong2*)&smu.s.As[k][tm * 8];
            ulonglong2 A1 = *(const ulonglong2*)&smu.s.As[k][tm * 8 + 4];
            ull ap[4] = {A0.x, A0.y, A1.x, A1.y};
            float4 b0 = *(const float4*)&smu.s.Bs[k][tx * 4];
            float4 b1 = *(const float4*)&smu.s.Bs[k][32 + tx * 4];
            ull bd[8] = {pk2(b0.x,b0.x), pk2(b0.y,b0.y), pk2(b0.z,b0.z), pk2(b0.w,b0.w),
                         pk2(b1.x,b1.x), pk2(b1.y,b1.y), pk2(b1.z,b1.z), pk2(b1.w,b1.w)};
#pragma unroll
            for (int i = 0; i < 4; ++i)
#pragma unroll
                for (int j = 0; j < 8; ++j)
                    acc[i][j] = fma2(ap[i], bd[j], acc[i][j]);
        }
        __syncthreads();
    }

    float qmf[8];
#pragma unroll
    for (int j = 0; j < 4; ++j) {
        qmf[j]     = (float)qmask[b * UU + tx * 4 + j];
        qmf[4 + j] = (float)qmask[b * UU + 32 + tx * 4 + j];
    }

#pragma unroll
    for (int r = 0; r < 8; ++r) {
        const int i = r >> 1;
        float s[8];
#pragma unroll
        for (int j = 0; j < 8; ++j) {
            float lo, hi; up2(acc[i][j], lo, hi);
            s[j] = (r & 1) ? hi : lo;
        }
        float x[8], mx = -3.4e38f;
#pragma unroll
        for (int j = 0; j < 8; ++j) { x[j] = s[j] * qmf[j]; mx = fmaxf(mx, x[j]); }
#pragma unroll
        for (int o = 1; o < 8; o <<= 1)
            mx = fmaxf(mx, __shfl_xor_sync(0xffffffffu, mx, o));
        float e[8], z = 0.f, zm = 0.f;
#pragma unroll
        for (int j = 0; j < 8; ++j) {
            e[j] = __expf(x[j] - mx);
            z += e[j]; zm += qmf[j] * e[j];
        }
#pragma unroll
        for (int o = 1; o < 8; o <<= 1) {
            z  += __shfl_xor_sync(0xffffffffu, z,  o);
            zm += __shfl_xor_sync(0xffffffffu, zm, o);
        }
        float inv = 1.0f / (zm + FEPS * z);
        const int ml = tm * 8 + r;
        const int m  = m0 + ml;
        if (m < NTK) {
            size_t off = ((size_t)b * NTK + m) * UU;
            *(float4*)(g_scores + off + tx * 4)      = make_float4(s[0], s[1], s[2], s[3]);
            *(float4*)(g_scores + off + 32 + tx * 4) = make_float4(s[4], s[5], s[6], s[7]);
        }
        *(float4*)&smu.sw[ml][tx * 4] =
            make_float4(qmf[0]*e[0]*inv, qmf[1]*e[1]*inv, qmf[2]*e[2]*inv, qmf[3]*e[3]*inv);
        *(float4*)&smu.sw[ml][32 + tx * 4] =
            make_float4(qmf[4]*e[4]*inv, qmf[5]*e[5]*inv, qmf[6]*e[6]*inv, qmf[7]*e[7]*inv);
    }
    __syncthreads();

    // coalesced transposed write: thread owns u-row, 64 m columns
    {
        const int u = tid & 63, mh = (tid >> 6) * 64;
        int rem = NTK - (m0 + mh);
        if (rem > 64) rem = 64;
        float* dst = g_attnT + ((size_t)b * UU + u) * NTK + m0 + mh;
        for (int c = 0; c < rem; c += 4) {
            float4 t;
            t.x = smu.sw[mh + c + 0][u];
            t.y = smu.sw[mh + c + 1][u];
            t.z = smu.sw[mh + c + 2][u];
            t.w = smu.sw[mh + c + 3][u];
            *(float4*)(dst + c) = t;
        }
    }
}

// =====================================================================
// K2: softmax over T per (b,n,u), masked by doc_mask -> g_wT
// =====================================================================
__global__ __launch_bounds__(256)
void k2_softT(const int* __restrict__ dmask)
{
    const int n = blockIdx.x, b = blockIdx.y;
    __shared__ float sdm[TT];
    __shared__ float red [4][64];
    __shared__ float red2[4][64];
    __shared__ float fmx[64], finv[64];

    const int tid = threadIdx.x;
    for (int t = tid; t < TT; t += 256)
        sdm[t] = (float)dmask[(b * NN + n) * TT + t];
    __syncthreads();

    const int u = tid & 63, sl = tid >> 6;
    const float* S = g_scores + ((size_t)b * NTK + n * TT) * UU;

    float mx = -3.4e38f;
    for (int t = sl; t < TT; t += 4)
        mx = fmaxf(mx, S[t * UU + u] * sdm[t]);
    red[sl][u] = mx;
    __syncthreads();
    if (tid < 64)
        fmx[u] = fmaxf(fmaxf(red[0][u], red[1][u]), fmaxf(red[2][u], red[3][u]));
    __syncthreads();

    float m = fmx[u];
    float z = 0.f, zm = 0.f;
    for (int t = sl; t < TT; t += 4) {
        float dm = sdm[t];
        float e = __expf(S[t * UU + u] * dm - m);
        z += e; zm += dm * e;
    }
    red[sl][u] = z; red2[sl][u] = zm;
    __syncthreads();
    if (tid < 64) {
        float Z  = red [0][u] + red [1][u] + red [2][u] + red [3][u];
        float Zm = red2[0][u] + red2[1][u] + red2[2][u] + red2[3][u];
        finv[u] = 1.0f / (Zm + FEPS * Z);
    }
    __syncthreads();

    float inv = finv[u];
    float* W = g_wT + ((size_t)b * NTK + n * TT) * UU;
    for (int t = sl; t < TT; t += 4) {
        float dm = sdm[t];
        float e = __expf(S[t * UU + u] * dm - m);
        W[t * UU + u] = dm * e * inv;
    }
}

// =====================================================================
// K3: part[b,n,u,h] = sum_t wT[t,u]*doc[t,h].  Tile U=64 x H=128, BK=32.
// grid (4, 20, 8), 128 threads, 8x8/thread. acc pairs along u.
// =====================================================================
__global__ __launch_bounds__(128)
void k3_part(const float* __restrict__ doc)
{
    const int hb = blockIdx.x, n = blockIdx.y, b = blockIdx.z;
    const int tid = threadIdx.x;
    const int tx = tid & 15, uy = tid >> 4;   // tx: h-group, uy: u-group (8 rows)
    const int h0 = hb * 128;

    __shared__ __align__(16) float Aw[32][68];
    __shared__ __align__(16) float Bd[32][132];

    const float* Wb = g_wT + ((size_t)b * NTK + n * TT) * UU;
    const float* Db = doc + ((size_t)b * NTK + n * TT) * HH + h0;

    const int tl = tid & 31, q4 = tid >> 5;

    ull acc[4][8];
#pragma unroll
    for (int i = 0; i < 4; ++i)
#pragma unroll
        for (int j = 0; j < 8; ++j) acc[i][j] = 0ull;

    for (int kk = 0; kk < TT; kk += 32) {
        int tsrc = kk + tl;
        bool dead = (tsrc >= TT);
        if (dead) tsrc = TT - 1;
        const float* Wr = Wb + (size_t)tsrc * UU + q4 * 16;
        const float* Dr = Db + (size_t)tsrc * HH + q4 * 32;
#pragma unroll
        for (int c = 0; c < 4; ++c) {
            float4 v = *(const float4*)(Wr + c * 4);
            if (dead) v = make_float4(0.f, 0.f, 0.f, 0.f);
            *(float4*)&Aw[tl][q4 * 16 + c * 4] = v;
        }
#pragma unroll
        for (int c = 0; c < 8; ++c) {
            float4 v = *(const float4*)(Dr + c * 4);
            *(float4*)&Bd[tl][q4 * 32 + c * 4] = v;
        }
        __syncthreads();
#pragma unroll
        for (int k = 0; k < 32; ++k) {
            ulonglong2 A0 = *(const ulonglong2*)&Aw[k][uy * 8];
            ulonglong2 A1 = *(const ulonglong2*)&Aw[k][uy * 8 + 4];
            ull ap[4] = {A0.x, A0.y, A1.x, A1.y};
            float4 b0 = *(const float4*)&Bd[k][tx * 4];
            float4 b1 = *(const float4*)&Bd[k][64 + tx * 4];
            ull bd[8] = {pk2(b0.x,b0.x), pk2(b0.y,b0.y), pk2(b0.z,b0.z), pk2(b0.w,b0.w),
                         pk2(b1.x,b1.x), pk2(b1.y,b1.y), pk2(b1.z,b1.z), pk2(b1.w,b1.w)};
#pragma unroll
            for (int i = 0; i < 4; ++i)
#pragma unroll
                for (int j = 0; j < 8; ++j)
                    acc[i][j] = fma2(ap[i], bd[j], acc[i][j]);
        }
        __syncthreads();
    }

#pragma unroll
    for (int i = 0; i < 4; ++i) {
        float lo[8], hi[8];
#pragma unroll
        for (int j = 0; j < 8; ++j) up2(acc[i][j], lo[j], hi[j]);
        const int u = uy * 8 + 2 * i;
        size_t base = (((size_t)(b * NN + n)) * UU + u) * HH + h0;
        *(float4*)(g_part + base + tx * 4)            = make_float4(lo[0], lo[1], lo[2], lo[3]);
        *(float4*)(g_part + base + 64 + tx * 4)       = make_float4(lo[4], lo[5], lo[6], lo[7]);
        *(float4*)(g_part + base + HH + tx * 4)       = make_float4(hi[0], hi[1], hi[2], hi[3]);
        *(float4*)(g_part + base + HH + 64 + tx * 4)  = make_float4(hi[4], hi[5], hi[6], hi[7]);
    }
}

// =====================================================================
// K3b: aggdoc = sum_n part.  float4-vectorized.  grid 256 x 256.
// =====================================================================
__global__ __launch_bounds__(256)
void k3b_reduce()
{
    int idx = blockIdx.x * 256 + threadIdx.x;         // < 65536
    int b = idx >> 13, r = idx & 8191;
    const float4* P = (const float4*)(g_part + (size_t)b * NN * UU * HH) + r;
    float4 s = make_float4(0.f, 0.f, 0.f, 0.f);
#pragma unroll
    for (int n = 0; n < NN; ++n) {
        float4 v = P[(size_t)n * (UU * HH / 4)];
        s.x += v.x; s.y += v.y; s.z += v.z; s.w += v.w;
    }
    ((float4*)g_aggdoc)[(size_t)b * (UU * HH / 4) + r] = s;
}

// =====================================================================
// K4: out[b,m,0:512] = attn@q ; out[b,m,512:1024] = attn@aggdoc.
// grid (94, 8), 64 threads. Tile M=64, K=64 resident; loop hb(8) x half(2).
// A staged once from g_attnT (natural rows). 8x8/thread, pairs along m.
// =====================================================================
__global__ __launch_bounds__(64)
void k4_out(const float* __restrict__ q, float* __restrict__ out)
{
    const int m0 = blockIdx.x * 64, b = blockIdx.y;
    const int tid = threadIdx.x;
    const int tx = tid & 7, tm = tid >> 3;

    __shared__ __align__(16) float As[64][68];   // [u][m]
    __shared__ __align__(16) float Bs[64][68];   // [u][h]

    // stage A once: thread owns u-row tid
    {
        const int mrem = NTK - m0;               // >= 48 always
        const float* Ar = g_attnT + ((size_t)b * UU + tid) * NTK + m0;
#pragma unroll
        for (int c = 0; c < 16; ++c) {
            int off = c * 4;
            if (off + 4 > mrem) off = mrem - 4;
            float4 v = *(const float4*)(Ar + off);
            *(float4*)&As[tid][off] = v;
        }
    }
    __syncthreads();

    const float* q_b = q        + (size_t)b * UU * HH;
    const float* a_b = g_aggdoc + (size_t)b * UU * HH;

    for (int hb = 0; hb < 8; ++hb) {
#pragma unroll
        for (int half = 0; half < 2; ++half) {
            const float* Bsrc = (half == 0 ? q_b : a_b) + hb * 64;
            {
                const float* Br = Bsrc + (size_t)tid * HH;
#pragma unroll
                for (int c = 0; c < 16; ++c)
                    *(float4*)&Bs[tid][c * 4] = *(const float4*)(Br + c * 4);
            }
            __syncthreads();

            ull acc[4][8];
#pragma unroll
            for (int i = 0; i < 4; ++i)
#pragma unroll
                for (int j = 0; j < 8; ++j) acc[i][j] = 0ull;

#pragma unroll 8
            for (int k = 0; k < 64; ++k) {
                ulonglong2 A0 = *(const ulonglong2*)&As[k][tm * 8];
                ulonglong2 A1 = *(const ulonglong2*)&As[k][tm * 8 + 4];
                ull ap[4] = {A0.x, A0.y, A1.x, A1.y};
                float4 b0 = *(const float4*)&Bs[k][tx * 4];
                float4 b1 = *(const float4*)&Bs[k][32 + tx * 4];
                ull bd[8] = {pk2(b0.x,b0.x), pk2(b0.y,b0.y), pk2(b0.z,b0.z), pk2(b0.w,b0.w),
                             pk2(b1.x,b1.x), pk2(b1.y,b1.y), pk2(b1.z,b1.z), pk2(b1.w,b1.w)};
#pragma unroll
                for (int i = 0; i < 4; ++i)
#pragma unroll
                    for (int j = 0; j < 8; ++j)
                        acc[i][j] = fma2(ap[i], bd[j], acc[i][j]);
            }

#pragma unroll
            for (int r = 0; r < 8; ++r) {
                const int m = m0 + tm * 8 + r;
                if (m < NTK) {
                    const int i = r >> 1;
                    float s[8];
#pragma unroll
                    for (int j = 0; j < 8; ++j) {
                        float lo, hi; up2(acc[i][j], lo, hi);
                        s[j] = (r & 1) ? hi : lo;
                    }
                    size_t base = ((size_t)b * NTK + m) * 1024 + half * 512 + hb * 64;
                    *(float4*)(out + base + tx * 4)      = make_float4(s[0], s[1], s[2], s[3]);
                    *(float4*)(out + base + 32 + tx * 4) = make_float4(s[4], s[5], s[6], s[7]);
                }
            }
            __syncthreads();
        }
    }
}

// =====================================================================
extern "C" void kernel_launch(void* const* d_in, const int* in_sizes, int n_in,
                              void* d_out, int out_size)
{
    const float* doc   = (const float*)d_in[0];   // B,N,T,H
    const float* q     = (const float*)d_in[1];   // B,U,H
    const int*   dmask = (const int*)  d_in[2];   // B,N,T
    const int*   qmask = (const int*)  d_in[3];   // B,U
    float* out = (float*)d_out;                   // B,N,T,2H

    k1_scores <<<dim3(47, BB), 128>>>(doc, q, qmask);
    k2_softT  <<<dim3(NN, BB), 256>>>(dmask);
    k3_part   <<<dim3(4, NN, BB), 128>>>(doc);
    k3b_reduce<<<256, 256>>>();
    k4_out    <<<dim3(94, BB), 64>>>(q, out);
}